// round 6
// baseline (speedup 1.0000x reference)
#include <cuda_runtime.h>
#include <math.h>
#include <cstdint>

// Output = 2*PE broadcast: 65536x64x16 fp32 = 256 MB pure stores.
// Pattern period 4 KB. Interleaved dual-engine writer, perfectly balanced:
//   grid = 1024. Even CTAs (512) push even 32KB chunks via cp.async.bulk
//   (8 chunks each, exact). Odd CTAs (512) write odd chunks with 256-bit
//   st.global.v8.f32 (Blackwell STG.256), 8 chunks each, exact.

#define CHUNK_BYTES   32768
#define CHUNK_FLOAT4  (CHUNK_BYTES / 16)   // 2048
#define GRID_CTAS     1024

__device__ __forceinline__ void stg_v8(float* p, float4 a, float4 b) {
    asm volatile("st.global.v8.f32 [%0], {%1,%2,%3,%4,%5,%6,%7,%8};"
                 :: "l"(p), "f"(a.x), "f"(a.y), "f"(a.z), "f"(a.w),
                    "f"(b.x), "f"(b.y), "f"(b.z), "f"(b.w) : "memory");
}

__global__ void __launch_bounds__(256)
pe_dual2_kernel(float* __restrict__ out, long long n_chunks) {
    __shared__ __align__(256) float4 smem[CHUNK_FLOAT4];   // 32 KB

    const int t = threadIdx.x;      // float4 index within 256-float4 period
    const int pos = t >> 2;
    const int c0  = (t & 3) * 4;

    float4 v;
    {
        const float ln1e4_over8 = 1.1512925464970229f;  // ln(10000)/8
        float vals[4];
        #pragma unroll
        for (int k = 0; k < 4; ++k) {
            int c = c0 + k;
            float div = (float)pos * expf(-(float)c * ln1e4_over8);
            float s, co;
            sincosf(div, &s, &co);
            vals[k] = 2.0f * ((c & 1) == 0 ? s : co);
        }
        v.x = vals[0]; v.y = vals[1]; v.z = vals[2]; v.w = vals[3];
    }

    const int role       = blockIdx.x & 1;        // 0 = TMA bulk, 1 = STG.256
    const long long r    = blockIdx.x >> 1;       // 0..511 within role
    const long long nR   = gridDim.x >> 1;        // 512

    if (role == 0) {
        // Stage one 32 KB repetition.
        #pragma unroll
        for (int p = 0; p < 8; ++p)
            smem[p * 256 + t] = v;
        __syncthreads();

        if (t == 0) {
            asm volatile("fence.proxy.async.shared::cta;" ::: "memory");
            uint32_t s_addr;
            asm("{ .reg .u64 a; cvta.to.shared.u64 a, %1; cvt.u32.u64 %0, a; }"
                : "=r"(s_addr) : "l"(smem));
            for (long long i = r; i * 2 < n_chunks; i += nR) {
                const char* dst = (const char*)out + (i * 2) * (long long)CHUNK_BYTES;
                asm volatile(
                    "cp.async.bulk.global.shared::cta.bulk_group [%0], [%1], %2;"
                    :: "l"(dst), "r"(s_addr), "n"(CHUNK_BYTES) : "memory");
            }
            asm volatile("cp.async.bulk.commit_group;" ::: "memory");
            asm volatile("cp.async.bulk.wait_group 0;" ::: "memory");
        }
    } else {
        // Thread t covers float4 slots {2t, 2t+1} of a 512-float4 double-period.
        // v depends only on (slot mod 256); compute both values directly.
        float4 va, vb;
        {
            const float ln1e4_over8 = 1.1512925464970229f;
            int slots[2] = { (2 * t) & 255, (2 * t + 1) & 255 };
            float4* outv[2] = { &va, &vb };
            #pragma unroll
            for (int sIdx = 0; sIdx < 2; ++sIdx) {
                int ss = slots[sIdx];
                int sp = ss >> 2;
                int sc0 = (ss & 3) * 4;
                float vals[4];
                #pragma unroll
                for (int k = 0; k < 4; ++k) {
                    int c = sc0 + k;
                    float div = (float)sp * expf(-(float)c * ln1e4_over8);
                    float s, co;
                    sincosf(div, &s, &co);
                    vals[k] = 2.0f * ((c & 1) == 0 ? s : co);
                }
                outv[sIdx]->x = vals[0]; outv[sIdx]->y = vals[1];
                outv[sIdx]->z = vals[2]; outv[sIdx]->w = vals[3];
            }
        }
        // Each chunk = 2048 float4 = 1024 v8-stores; 256 threads -> 4 per thread.
        for (long long i = r; i * 2 + 1 < n_chunks; i += nR) {
            float* base = out + (i * 2 + 1) * (long long)(CHUNK_FLOAT4 * 4);
            #pragma unroll
            for (int p = 0; p < 4; ++p)
                stg_v8(base + (p * 256 + t) * 8, va, vb);
        }
    }
}

// Tail writer (not expected for this shape).
__global__ void pe_tail_kernel(float* __restrict__ out,
                               long long start_f, long long total_f) {
    long long i = start_f + blockIdx.x * 256LL + threadIdx.x;
    if (i >= total_f) return;
    const float ln1e4_over8 = 1.1512925464970229f;
    int rr = (int)(i & 1023);
    int pos = rr >> 4;
    int c = rr & 15;
    float div = (float)pos * expf(-(float)c * ln1e4_over8);
    float s, co;
    sincosf(div, &s, &co);
    out[i] = 2.0f * ((c & 1) == 0 ? s : co);
}

extern "C" void kernel_launch(void* const* d_in, const int* in_sizes, int n_in,
                              void* d_out, int out_size) {
    (void)d_in; (void)in_sizes; (void)n_in;
    long long total_bytes = (long long)out_size * 4;
    long long n_chunks = total_bytes / CHUNK_BYTES;      // 8192 for 256 MB
    long long rem_bytes = total_bytes - n_chunks * CHUNK_BYTES;

    if (n_chunks > 0) {
        int grid = GRID_CTAS;
        if ((long long)grid > n_chunks * 2) grid = (int)(n_chunks * 2);
        pe_dual2_kernel<<<grid, 256>>>((float*)d_out, n_chunks);
    }
    if (rem_bytes > 0) {
        long long start_f = n_chunks * (CHUNK_BYTES / 4);
        long long rem_f = rem_bytes / 4;
        int blocks = (int)((rem_f + 255) / 256);
        pe_tail_kernel<<<blocks, 256>>>((float*)d_out, start_f, (long long)out_size);
    }
}